// round 5
// baseline (speedup 1.0000x reference)
#include <cuda_runtime.h>
#include <cuda_fp16.h>
#include <cstdint>

// ---------------------------------------------------------------------------
// CrossAttentionDecoder, fp16 tensor-core pipeline (fp32 accumulate),
// ldmatrix fragment loads (4x fewer LDS wavefronts than scalar loads).
//   K1 proj  : g_Q  = half((x @ Wq^T) * 0.125)
//   K2 qk    : g_QK[b,h,i,:] = half(g_Q[b,i,h*64:+64] @ Wk[h*64:+64,:])
//   K3 attn  : per batch: scores = qk @ l^T (masked) -> softmax ->
//              g_AL = half(attn @ l)
//   K4 ov    : g_OV[:, h*64:+64] = half(g_AL_h @ Wv_h^T)
//   K5 proj  : out = g_OV @ Wo^T + bo   (fp32 out)
// ---------------------------------------------------------------------------

#define DIM 512
#define NLAT 128
#define NTOK 16
#define NHEAD 8
#define DH 64
#define NB 1024

__device__ __half g_Q [(size_t)NB * NTOK * DIM];
__device__ __half g_QK[(size_t)NB * NHEAD * NTOK * DIM];
__device__ __half g_AL[(size_t)NB * NHEAD * NTOK * DIM];
__device__ __half g_OV[(size_t)NB * NTOK * DIM];

#define PROJ_SMEM_H (128 * 72 + 64 * 72)
#define QK_SMEM_H   (128 * 72 + 64 * 72)
#define OV_SMEM_H   (128 * 72 + 64 * 72)
#define ATTN_SMEM_H (128 * 72 + 128 * 72 + 128 * 136)

__device__ __forceinline__ uint32_t packh2(float a, float b) {
    __half2 h = __floats2half2_rn(a, b);
    return *reinterpret_cast<uint32_t*>(&h);
}
__device__ __forceinline__ uint2 pack4(float4 v) {
    return make_uint2(packh2(v.x, v.y), packh2(v.z, v.w));
}
__device__ __forceinline__ void mma_fp16(float* c, uint32_t a0, uint32_t a1,
                                         uint32_t a2, uint32_t a3,
                                         uint32_t b0, uint32_t b1) {
    asm volatile(
        "mma.sync.aligned.m16n8k16.row.col.f32.f16.f16.f32 "
        "{%0,%1,%2,%3}, {%4,%5,%6,%7}, {%8,%9}, {%0,%1,%2,%3};\n"
        : "+f"(c[0]), "+f"(c[1]), "+f"(c[2]), "+f"(c[3])
        : "r"(a0), "r"(a1), "r"(a2), "r"(a3), "r"(b0), "r"(b1));
}
// ldmatrix x4: lanes 0-15 -> rows 0-15 at col k0; lanes 16-31 -> rows at k0+8.
__device__ __forceinline__ void ldsm_x4(uint32_t& r0, uint32_t& r1,
                                        uint32_t& r2, uint32_t& r3, uint32_t a) {
    asm volatile("ldmatrix.sync.aligned.m8n8.x4.shared.b16 {%0,%1,%2,%3}, [%4];"
        : "=r"(r0), "=r"(r1), "=r"(r2), "=r"(r3) : "r"(a));
}
__device__ __forceinline__ uint32_t sm_u32(const void* p) {
    return (uint32_t)__cvta_generic_to_shared(p);
}

// ---------------------------------------------------------------------------
// K1/K5: C[M,512] = scale * A @ W^T (+bias). Block 128m x 64n.
// ---------------------------------------------------------------------------
__global__ __launch_bounds__(256) void proj_kernel(
    const float* __restrict__ A32, const float* __restrict__ W,
    float* __restrict__ Cout, const float* __restrict__ bias,
    float scale, int mode)
{
    extern __shared__ __half smh[];
    __half* As = smh;               // [128][72]
    __half* Ws = smh + 128 * 72;    // [64][72]  Ws[n][k]

    const int n0 = blockIdx.x * 64;
    const int m0 = blockIdx.y * 128;
    const int tid = threadIdx.x;
    const int warp = tid >> 5, lane = tid & 31;
    const int g = lane >> 2, t = lane & 3;
    const int mw = warp * 16;
    const int l15 = lane & 15, lhi = (lane >> 4) * 8;

    const uint32_t a_base = sm_u32(As) + (uint32_t)((mw + l15) * 72 + lhi) * 2;
    const uint32_t b_base = sm_u32(Ws) + (uint32_t)(l15 * 72 + lhi) * 2;

    float c[8][4];
#pragma unroll
    for (int f = 0; f < 8; f++)
#pragma unroll
        for (int e = 0; e < 4; e++) c[f][e] = 0.f;

    for (int kc = 0; kc < 8; kc++) {
        const int k0g = kc * 64;
        if (mode == 0) {
#pragma unroll
            for (int it = 0; it < 8; it++) {
                int idx = tid + it * 256;
                int r = idx >> 4, c4 = idx & 15;
                float4 v = *reinterpret_cast<const float4*>(
                    A32 + (size_t)(m0 + r) * DIM + k0g + c4 * 4);
                *reinterpret_cast<uint2*>(As + r * 72 + c4 * 4) = pack4(v);
            }
        } else {
#pragma unroll
            for (int it = 0; it < 4; it++) {
                int idx = tid + it * 256;
                int r = idx >> 3, q = idx & 7;
                uint4 v = *reinterpret_cast<const uint4*>(
                    g_OV + (size_t)(m0 + r) * DIM + k0g + q * 8);
                *reinterpret_cast<uint4*>(As + r * 72 + q * 8) = v;
            }
        }
#pragma unroll
        for (int it = 0; it < 4; it++) {
            int idx = tid + it * 256;
            int r = idx >> 4, c4 = idx & 15;
            float4 v = *reinterpret_cast<const float4*>(
                W + (size_t)(n0 + r) * DIM + k0g + c4 * 4);
            *reinterpret_cast<uint2*>(Ws + r * 72 + c4 * 4) = pack4(v);
        }
        __syncthreads();
#pragma unroll
        for (int ks = 0; ks < 4; ks++) {
            const int k0 = ks * 16;
            uint32_t a0, a1, a2, a3;
            ldsm_x4(a0, a1, a2, a3, a_base + k0 * 2);
#pragma unroll
            for (int fp = 0; fp < 4; fp++) {
                uint32_t b0, b1, b2, b3;
                ldsm_x4(b0, b1, b2, b3, b_base + (fp * 16 * 72 + k0) * 2);
                mma_fp16(c[2 * fp],     a0, a1, a2, a3, b0, b2);
                mma_fp16(c[2 * fp + 1], a0, a1, a2, a3, b1, b3);
            }
        }
        __syncthreads();
    }
#pragma unroll
    for (int f = 0; f < 8; f++) {
        const int col = n0 + f * 8 + 2 * t;
        const int row0 = m0 + mw + g;
        if (mode == 0) {
            *reinterpret_cast<uint32_t*>(g_Q + (size_t)row0 * DIM + col) =
                packh2(c[f][0] * scale, c[f][1] * scale);
            *reinterpret_cast<uint32_t*>(g_Q + (size_t)(row0 + 8) * DIM + col) =
                packh2(c[f][2] * scale, c[f][3] * scale);
        } else {
            float b0 = bias[col], b1 = bias[col + 1];
            *reinterpret_cast<float2*>(Cout + (size_t)row0 * DIM + col) =
                make_float2(c[f][0] + b0, c[f][1] + b1);
            *reinterpret_cast<float2*>(Cout + (size_t)(row0 + 8) * DIM + col) =
                make_float2(c[f][2] + b0, c[f][3] + b1);
        }
    }
}

// ---------------------------------------------------------------------------
// K2: g_QK = g_Q_h @ Wk_h (K=64). grid (8 e-chunks, 128 mtiles, 8 heads)
// ---------------------------------------------------------------------------
__global__ __launch_bounds__(256) void qk_kernel(const float* __restrict__ Wk)
{
    extern __shared__ __half smh[];
    __half* As  = smh;              // [128][72]
    __half* BsT = smh + 128 * 72;   // [64][72]  BsT[n][k] = Wk[h64+k][n0+n]

    const int n0 = blockIdx.x * 64;
    const int m0 = blockIdx.y * 128;
    const int h  = blockIdx.z;
    const int tid = threadIdx.x;
    const int warp = tid >> 5, lane = tid & 31;
    const int g = lane >> 2, t = lane & 3;
    const int mw = warp * 16;
    const int l15 = lane & 15, lhi = (lane >> 4) * 8;

#pragma unroll
    for (int it = 0; it < 4; it++) {
        int idx = tid + it * 256;
        int r = idx >> 3, q = idx & 7;
        uint4 v = *reinterpret_cast<const uint4*>(
            g_Q + (size_t)(m0 + r) * DIM + h * DH + q * 8);
        *reinterpret_cast<uint4*>(As + r * 72 + q * 8) = v;
    }
#pragma unroll
    for (int it = 0; it < 4; it++) {
        int idx = tid + it * 256;
        int k = idx >> 4, q = idx & 15;
        float4 v = *reinterpret_cast<const float4*>(
            Wk + (size_t)(h * DH + k) * DIM + n0 + q * 4);
        BsT[(q * 4 + 0) * 72 + k] = __float2half_rn(v.x);
        BsT[(q * 4 + 1) * 72 + k] = __float2half_rn(v.y);
        BsT[(q * 4 + 2) * 72 + k] = __float2half_rn(v.z);
        BsT[(q * 4 + 3) * 72 + k] = __float2half_rn(v.w);
    }
    __syncthreads();

    const uint32_t a_base = sm_u32(As) + (uint32_t)((mw + l15) * 72 + lhi) * 2;
    const uint32_t b_base = sm_u32(BsT) + (uint32_t)(l15 * 72 + lhi) * 2;

    float c[8][4];
#pragma unroll
    for (int f = 0; f < 8; f++)
#pragma unroll
        for (int e = 0; e < 4; e++) c[f][e] = 0.f;

#pragma unroll
    for (int ks = 0; ks < 4; ks++) {
        const int k0 = ks * 16;
        uint32_t a0, a1, a2, a3;
        ldsm_x4(a0, a1, a2, a3, a_base + k0 * 2);
#pragma unroll
        for (int fp = 0; fp < 4; fp++) {
            uint32_t b0, b1, b2, b3;
            ldsm_x4(b0, b1, b2, b3, b_base + (fp * 16 * 72 + k0) * 2);
            mma_fp16(c[2 * fp],     a0, a1, a2, a3, b0, b2);
            mma_fp16(c[2 * fp + 1], a0, a1, a2, a3, b1, b3);
        }
    }

    const int bb = (m0 + mw) >> 4;
#pragma unroll
    for (int f = 0; f < 8; f++) {
        const int col = n0 + f * 8 + 2 * t;
        size_t o0 = (((size_t)bb * NHEAD + h) * NTOK + g) * DIM + col;
        size_t o1 = (((size_t)bb * NHEAD + h) * NTOK + g + 8) * DIM + col;
        *reinterpret_cast<uint32_t*>(g_QK + o0) = packh2(c[f][0], c[f][1]);
        *reinterpret_cast<uint32_t*>(g_QK + o1) = packh2(c[f][2], c[f][3]);
    }
}

// ---------------------------------------------------------------------------
// K3: per-batch attention. warp = head.
// ---------------------------------------------------------------------------
__global__ __launch_bounds__(256) void attn_kernel(const float* __restrict__ l)
{
    extern __shared__ __half smh[];
    __half* l_s  = smh;                    // A: [128][72]; B: l_t [64][136]
    __half* qk_s = smh + 128 * 72;         // [128][72]
    __half* s_s  = qk_s + 128 * 72;        // [128][136]

    const int b = blockIdx.x;
    const int m = b & (NLAT - 1);
    const int njt = (m >> 5) + 1;
    const int rows = njt << 5;

    const int tid = threadIdx.x;
    const int h = tid >> 5, lane = tid & 31;
    const int g = lane >> 2, t = lane & 3;
    const int l15 = lane & 15, lhi = (lane >> 4) * 8;

    const float*  lb  = l + (size_t)b * NLAT * DIM;
    const __half* qkb = g_QK + (size_t)b * NHEAD * NTOK * DIM;

    const uint32_t aq_base = sm_u32(qk_s) + (uint32_t)((h * 16 + l15) * 72 + lhi) * 2;
    const uint32_t blA_base = sm_u32(l_s) + (uint32_t)(l15 * 72 + lhi) * 2;

    float cs[16][4];
#pragma unroll
    for (int f = 0; f < 16; f++)
#pragma unroll
        for (int e = 0; e < 4; e++) cs[f][e] = 0.f;

    // ---- phase A: scores = qk @ l^T ----
    for (int ec = 0; ec < 8; ec++) {
        const int e0 = ec * 64;
#pragma unroll
        for (int it = 0; it < 4; it++) {
            int idx = tid + it * 256;
            int r = idx >> 3, q = idx & 7;
            uint4 v = *reinterpret_cast<const uint4*>(
                qkb + (size_t)r * DIM + e0 + q * 8);
            *reinterpret_cast<uint4*>(qk_s + r * 72 + q * 8) = v;
        }
#pragma unroll
        for (int it = 0; it < 8; it++) {
            int idx = tid + it * 256;
            int r = idx >> 4, c4 = idx & 15;
            if (r < rows) {
                float4 v = *reinterpret_cast<const float4*>(
                    lb + (size_t)r * DIM + e0 + c4 * 4);
                *reinterpret_cast<uint2*>(l_s + r * 72 + c4 * 4) = pack4(v);
            }
        }
        __syncthreads();
#pragma unroll
        for (int ks = 0; ks < 4; ks++) {
            const int k0 = ks * 16;
            uint32_t a0, a1, a2, a3;
            ldsm_x4(a0, a1, a2, a3, aq_base + k0 * 2);
#pragma unroll
            for (int jt = 0; jt < 4; jt++) {
                if (jt < njt) {
#pragma unroll
                    for (int jp = 0; jp < 2; jp++) {
                        uint32_t b0, b1, b2, b3;
                        ldsm_x4(b0, b1, b2, b3,
                                blA_base + ((jt * 32 + jp * 16) * 72 + k0) * 2);
                        mma_fp16(cs[jt * 4 + jp * 2],     a0, a1, a2, a3, b0, b2);
                        mma_fp16(cs[jt * 4 + jp * 2 + 1], a0, a1, a2, a3, b1, b3);
                    }
                }
            }
        }
        __syncthreads();
    }

    // ---- masked softmax ----
    float mx0 = -1e30f, mx1 = -1e30f;
#pragma unroll
    for (int f = 0; f < 16; f++) {
        const int jb = f * 8 + 2 * t;
#pragma unroll
        for (int e = 0; e < 2; e++) {
            if (jb + e > m) { cs[f][e] = -1e30f; cs[f][2 + e] = -1e30f; }
            mx0 = fmaxf(mx0, cs[f][e]);
            mx1 = fmaxf(mx1, cs[f][2 + e]);
        }
    }
    mx0 = fmaxf(mx0, __shfl_xor_sync(0xffffffffu, mx0, 1));
    mx0 = fmaxf(mx0, __shfl_xor_sync(0xffffffffu, mx0, 2));
    mx1 = fmaxf(mx1, __shfl_xor_sync(0xffffffffu, mx1, 1));
    mx1 = fmaxf(mx1, __shfl_xor_sync(0xffffffffu, mx1, 2));
    float s0 = 0.f, s1 = 0.f;
#pragma unroll
    for (int f = 0; f < 16; f++)
#pragma unroll
        for (int e = 0; e < 2; e++) {
            cs[f][e] = __expf(cs[f][e] - mx0);         s0 += cs[f][e];
            cs[f][2 + e] = __expf(cs[f][2 + e] - mx1); s1 += cs[f][2 + e];
        }
    s0 += __shfl_xor_sync(0xffffffffu, s0, 1);
    s0 += __shfl_xor_sync(0xffffffffu, s0, 2);
    s1 += __shfl_xor_sync(0xffffffffu, s1, 1);
    s1 += __shfl_xor_sync(0xffffffffu, s1, 2);
    const float i0 = 1.f / s0, i1 = 1.f / s1;
#pragma unroll
    for (int f = 0; f < 16; f++) {
        const int jb = f * 8 + 2 * t;
        *reinterpret_cast<uint32_t*>(s_s + (h * 16 + g) * 136 + jb) =
            packh2(cs[f][0] * i0, cs[f][1] * i0);
        *reinterpret_cast<uint32_t*>(s_s + (h * 16 + g + 8) * 136 + jb) =
            packh2(cs[f][2] * i1, cs[f][3] * i1);
    }
    // s_s rows are warp-private (same warp writes and reads them).

    // ---- phase B: AL = attn @ l ----
    __half* l_t = l_s;                     // [64][136]  l_t[e][j]
    const uint32_t as_base = sm_u32(s_s) + (uint32_t)((h * 16 + l15) * 136 + lhi) * 2;
    const uint32_t blB_base = sm_u32(l_t) + (uint32_t)(l15 * 136 + lhi) * 2;

    for (int ec = 0; ec < 8; ec++) {
        const int e0 = ec * 64;
        __syncthreads();
#pragma unroll
        for (int it = 0; it < 8; it++) {
            int idx = tid + it * 256;
            int j = idx >> 4, c4 = idx & 15;
            if (j < rows) {
                float4 v = *reinterpret_cast<const float4*>(
                    lb + (size_t)j * DIM + e0 + c4 * 4);
                l_t[(c4 * 4 + 0) * 136 + j] = __float2half_rn(v.x);
                l_t[(c4 * 4 + 1) * 136 + j] = __float2half_rn(v.y);
                l_t[(c4 * 4 + 2) * 136 + j] = __float2half_rn(v.z);
                l_t[(c4 * 4 + 3) * 136 + j] = __float2half_rn(v.w);
            }
        }
        __syncthreads();

        float co[8][4];
#pragma unroll
        for (int en = 0; en < 8; en++)
#pragma unroll
            for (int e = 0; e < 4; e++) co[en][e] = 0.f;

        for (int jk = 0; jk < njt * 2; jk++) {
            const int k0 = jk * 16;
            uint32_t a0, a1, a2, a3;
            ldsm_x4(a0, a1, a2, a3, as_base + k0 * 2);
#pragma unroll
            for (int ep = 0; ep < 4; ep++) {
                uint32_t b0, b1, b2, b3;
                ldsm_x4(b0, b1, b2, b3, blB_base + (ep * 16 * 136 + k0) * 2);
                mma_fp16(co[2 * ep],     a0, a1, a2, a3, b0, b2);
                mma_fp16(co[2 * ep + 1], a0, a1, a2, a3, b1, b3);
            }
        }
#pragma unroll
        for (int en = 0; en < 8; en++) {
            const int col = e0 + en * 8 + 2 * t;
            size_t o0 = ((size_t)b * (NHEAD * NTOK) + h * 16 + g) * DIM + col;
            size_t o1 = ((size_t)b * (NHEAD * NTOK) + h * 16 + g + 8) * DIM + col;
            *reinterpret_cast<uint32_t*>(g_AL + o0) = packh2(co[en][0], co[en][1]);
            *reinterpret_cast<uint32_t*>(g_AL + o1) = packh2(co[en][2], co[en][3]);
        }
    }
}

// ---------------------------------------------------------------------------
// K4: g_OV = g_AL_h @ Wv_h^T  (K=512, N=64). grid (128, 8)
// ---------------------------------------------------------------------------
__global__ __launch_bounds__(256) void ov_kernel(const float* __restrict__ Wv)
{
    extern __shared__ __half smh[];
    __half* As = smh;               // [128][72]
    __half* Ws = smh + 128 * 72;    // [64][72]  Ws[d][k]

    const int bt = blockIdx.x;
    const int h  = blockIdx.y;
    const int tid = threadIdx.x;
    const int warp = tid >> 5, lane = tid & 31;
    const int g = lane >> 2, t = lane & 3;
    const int mw = warp * 16;
    const int l15 = lane & 15, lhi = (lane >> 4) * 8;

    const uint32_t a_base = sm_u32(As) + (uint32_t)((mw + l15) * 72 + lhi) * 2;
    const uint32_t b_base = sm_u32(Ws) + (uint32_t)(l15 * 72 + lhi) * 2;

    float c[8][4];
#pragma unroll
    for (int f = 0; f < 8; f++)
#pragma unroll
        for (int e = 0; e < 4; e++) c[f][e] = 0.f;

    for (int kc = 0; kc < 8; kc++) {
        const int k0g = kc * 64;
#pragma unroll
        for (int it = 0; it < 4; it++) {
            int idx = tid + it * 256;
            int r = idx >> 3, q = idx & 7;
            size_t gr = (((size_t)(bt * 8 + (r >> 4)) * NHEAD + h) * NTOK + (r & 15));
            uint4 v = *reinterpret_cast<const uint4*>(
                g_AL + gr * DIM + k0g + q * 8);
            *reinterpret_cast<uint4*>(As + r * 72 + q * 8) = v;
        }
#pragma unroll
        for (int it = 0; it < 4; it++) {
            int idx = tid + it * 256;
            int d = idx >> 4, c4 = idx & 15;
            float4 v = *reinterpret_cast<const float4*>(
                Wv + (size_t)(h * DH + d) * DIM + k0g + c4 * 4);
            *reinterpret_cast<uint2*>(Ws + d * 72 + c4 * 4) = pack4(v);
        }
        __syncthreads();
#pragma unroll
        for (int ks = 0; ks < 4; ks++) {
            const int k0 = ks * 16;
            uint32_t a0, a1, a2, a3;
            ldsm_x4(a0, a1, a2, a3, a_base + k0 * 2);
#pragma unroll
            for (int fp = 0; fp < 4; fp++) {
                uint32_t b0, b1, b2, b3;
                ldsm_x4(b0, b1, b2, b3, b_base + (fp * 16 * 72 + k0) * 2);
                mma_fp16(c[2 * fp],     a0, a1, a2, a3, b0, b2);
                mma_fp16(c[2 * fp + 1], a0, a1, a2, a3, b1, b3);
            }
        }
        __syncthreads();
    }

    const int bb = bt * 8 + warp;
#pragma unroll
    for (int f = 0; f < 8; f++) {
        const int col = h * DH + f * 8 + 2 * t;
        size_t o0 = ((size_t)bb * NTOK + g) * DIM + col;
        size_t o1 = ((size_t)bb * NTOK + g + 8) * DIM + col;
        *reinterpret_cast<uint32_t*>(g_OV + o0) = packh2(c[f][0], c[f][1]);
        *reinterpret_cast<uint32_t*>(g_OV + o1) = packh2(c[f][2], c[f][3]);
    }
}

// ---------------------------------------------------------------------------
extern "C" void kernel_launch(void* const* d_in, const int* in_sizes, int n_in,
                              void* d_out, int out_size)
{
    const float* x  = (const float*)d_in[0];
    const float* l  = (const float*)d_in[1];
    const float* Wq = (const float*)d_in[2];
    const float* Wk = (const float*)d_in[3];
    const float* Wv = (const float*)d_in[4];
    const float* Wo = (const float*)d_in[5];
    const float* bo = (const float*)d_in[6];
    float* out = (float*)d_out;

    const int smem_proj = PROJ_SMEM_H * 2;
    const int smem_qk   = QK_SMEM_H * 2;
    const int smem_attn = ATTN_SMEM_H * 2;
    const int smem_ov   = OV_SMEM_H * 2;

    cudaFuncSetAttribute(proj_kernel, cudaFuncAttributeMaxDynamicSharedMemorySize, smem_proj);
    cudaFuncSetAttribute(qk_kernel,   cudaFuncAttributeMaxDynamicSharedMemorySize, smem_qk);
    cudaFuncSetAttribute(attn_kernel, cudaFuncAttributeMaxDynamicSharedMemorySize, smem_attn);
    cudaFuncSetAttribute(ov_kernel,   cudaFuncAttributeMaxDynamicSharedMemorySize, smem_ov);

    proj_kernel<<<dim3(8, 128), 256, smem_proj>>>(x, Wq, nullptr, nullptr, 0.125f, 0);
    qk_kernel<<<dim3(8, 128, 8), 256, smem_qk>>>(Wk);
    attn_kernel<<<1024, 256, smem_attn>>>(l);
    ov_kernel<<<dim3(128, 8), 256, smem_ov>>>(Wv);
    proj_kernel<<<dim3(8, 128), 256, smem_proj>>>(nullptr, Wo, out, bo, 1.0f, 1);
}

// round 9
// speedup vs baseline: 1.3215x; 1.3215x over previous
#include <cuda_runtime.h>
#include <cuda_fp16.h>
#include <cstdint>

// ---------------------------------------------------------------------------
// CrossAttentionDecoder fp16 pipeline, cp.async double-buffered GEMMs.
//   K0 prep  : fp16 copies: g_X = x, g_Wqh = 0.125*Wq, g_Wkh/g_Wvh/g_Woh
//   K1 proj  : g_Q  = g_X @ g_Wqh^T            (scale folded into Wq)
//   K2 qk    : g_QK[b,h,i,:] = g_Q[b,i,h64:+64] @ Wk[h64:+64,:]
//   K3 attn  : per batch: scores = qk @ l^T (masked) -> softmax -> g_AL = attn @ l
//   K4 ov    : g_OV[:, h64:+64] = g_AL_h @ Wv_h^T   (double-buffered)
//   K5 proj  : out = g_OV @ g_Woh^T + bo  (fp32)
// NOTE: device scratch globals are referenced ONLY from device code (host-side
// symbol addresses are invalid — that was the R6 bug).
// ---------------------------------------------------------------------------

#define DIM 512
#define NLAT 128
#define NTOK 16
#define NHEAD 8
#define DH 64
#define NB 1024

__device__ __half g_X  [(size_t)NB * NTOK * DIM];
__device__ __half g_Wqh[DIM * DIM];
__device__ __half g_Wkh[DIM * DIM];
__device__ __half g_Wvh[DIM * DIM];
__device__ __half g_Woh[DIM * DIM];
__device__ __half g_Q [(size_t)NB * NTOK * DIM];
__device__ __half g_QK[(size_t)NB * NHEAD * NTOK * DIM];
__device__ __half g_AL[(size_t)NB * NHEAD * NTOK * DIM];
__device__ __half g_OV[(size_t)NB * NTOK * DIM];

#define GEMM_BUF_H (128 * 72 + 64 * 72)          // one pipeline stage (halves)
#define GEMM_SMEM  (2 * GEMM_BUF_H * 2)          // bytes, double buffered
#define QK_SMEM    ((128 * 72 + 64 * 72) * 2)    // bytes, single stage
#define ATTN_SMEM_H (128 * 72 + 128 * 72 + 128 * 136)

__device__ __forceinline__ uint32_t packh2(float a, float b) {
    __half2 h = __floats2half2_rn(a, b);
    return *reinterpret_cast<uint32_t*>(&h);
}
__device__ __forceinline__ uint2 pack4(float4 v) {
    return make_uint2(packh2(v.x, v.y), packh2(v.z, v.w));
}
__device__ __forceinline__ void mma_fp16(float* c, uint32_t a0, uint32_t a1,
                                         uint32_t a2, uint32_t a3,
                                         uint32_t b0, uint32_t b1) {
    asm volatile(
        "mma.sync.aligned.m16n8k16.row.col.f32.f16.f16.f32 "
        "{%0,%1,%2,%3}, {%4,%5,%6,%7}, {%8,%9}, {%0,%1,%2,%3};\n"
        : "+f"(c[0]), "+f"(c[1]), "+f"(c[2]), "+f"(c[3])
        : "r"(a0), "r"(a1), "r"(a2), "r"(a3), "r"(b0), "r"(b1));
}
__device__ __forceinline__ void ldsm_x4(uint32_t& r0, uint32_t& r1,
                                        uint32_t& r2, uint32_t& r3, uint32_t a) {
    asm volatile("ldmatrix.sync.aligned.m8n8.x4.shared.b16 {%0,%1,%2,%3}, [%4];"
        : "=r"(r0), "=r"(r1), "=r"(r2), "=r"(r3) : "r"(a));
}
__device__ __forceinline__ void ldsm_x4t(uint32_t& r0, uint32_t& r1,
                                         uint32_t& r2, uint32_t& r3, uint32_t a) {
    asm volatile("ldmatrix.sync.aligned.m8n8.x4.trans.shared.b16 {%0,%1,%2,%3}, [%4];"
        : "=r"(r0), "=r"(r1), "=r"(r2), "=r"(r3) : "r"(a));
}
__device__ __forceinline__ uint32_t sm_u32(const void* p) {
    return (uint32_t)__cvta_generic_to_shared(p);
}
__device__ __forceinline__ void cp16(uint32_t smem_dst, const void* gsrc) {
    asm volatile("cp.async.cg.shared.global [%0], [%1], 16;"
                 :: "r"(smem_dst), "l"(gsrc));
}
__device__ __forceinline__ void cp_commit() {
    asm volatile("cp.async.commit_group;");
}

// ---------------------------------------------------------------------------
// K0: fp16 conversions. i covers x (2M float4) then 4 weights (64K float4 each)
// ---------------------------------------------------------------------------
__global__ __launch_bounds__(256) void prep_kernel(
    const float* __restrict__ x,  const float* __restrict__ Wq,
    const float* __restrict__ Wk, const float* __restrict__ Wv,
    const float* __restrict__ Wo)
{
    int i = blockIdx.x * 256 + threadIdx.x;
    const float* src; __half* dst; float scale = 1.f; int off;
    const int NX4 = (NB * NTOK * DIM) / 4;       // 2097152
    if (i < NX4) { src = x; dst = g_X; off = i; }
    else {
        int j = i - NX4; int w = j >> 16; off = j & 65535;
        if      (w == 0) { src = Wq; dst = g_Wqh; scale = 0.125f; }
        else if (w == 1) { src = Wk; dst = g_Wkh; }
        else if (w == 2) { src = Wv; dst = g_Wvh; }
        else             { src = Wo; dst = g_Woh; }
    }
    float4 v = reinterpret_cast<const float4*>(src)[off];
    v.x *= scale; v.y *= scale; v.z *= scale; v.w *= scale;
    reinterpret_cast<uint2*>(dst)[off] = pack4(v);
}

// ---------------------------------------------------------------------------
// K1/K5: mode 0: g_Q = g_X @ g_Wqh^T.  mode 1: Cf = g_OV @ g_Woh^T + bias.
// Double-buffered cp.async. Block 128m x 64n.
// ---------------------------------------------------------------------------
__global__ __launch_bounds__(256) void proj16_kernel(
    int mode, float* __restrict__ Cf, const float* __restrict__ bias)
{
    extern __shared__ __half smh[];
    const __half* A = mode ? g_OV : g_X;
    const __half* W = mode ? g_Woh : g_Wqh;

    const int n0 = blockIdx.x * 64;
    const int m0 = blockIdx.y * 128;
    const int tid = threadIdx.x;
    const int warp = tid >> 5, lane = tid & 31;
    const int g = lane >> 2, t = lane & 3;
    const int mw = warp * 16;
    const int l15 = lane & 15, lhi = (lane >> 4) * 8;

    auto stage = [&](int kc, int s) {
        __half* As = smh + s * GEMM_BUF_H;
        __half* Ws = As + 128 * 72;
        const int k0g = kc * 64;
#pragma unroll
        for (int it = 0; it < 4; it++) {
            int idx = tid + it * 256; int r = idx >> 3, q = idx & 7;
            cp16(sm_u32(As + r * 72 + q * 8),
                 A + (size_t)(m0 + r) * DIM + k0g + q * 8);
        }
#pragma unroll
        for (int it = 0; it < 2; it++) {
            int idx = tid + it * 256; int r = idx >> 3, q = idx & 7;
            cp16(sm_u32(Ws + r * 72 + q * 8),
                 W + (size_t)(n0 + r) * DIM + k0g + q * 8);
        }
        cp_commit();
    };

    float c[8][4];
#pragma unroll
    for (int f = 0; f < 8; f++)
#pragma unroll
        for (int e = 0; e < 4; e++) c[f][e] = 0.f;

    stage(0, 0);
    for (int kc = 0; kc < 8; kc++) {
        if (kc < 7) {
            stage(kc + 1, (kc + 1) & 1);
            asm volatile("cp.async.wait_group 1;");
        } else {
            asm volatile("cp.async.wait_group 0;");
        }
        __syncthreads();
        __half* As = smh + (kc & 1) * GEMM_BUF_H;
        __half* Ws = As + 128 * 72;
        const uint32_t a_base = sm_u32(As) + (uint32_t)((mw + l15) * 72 + lhi) * 2;
        const uint32_t b_base = sm_u32(Ws) + (uint32_t)(l15 * 72 + lhi) * 2;
#pragma unroll
        for (int ks = 0; ks < 4; ks++) {
            const int k0 = ks * 16;
            uint32_t a0, a1, a2, a3;
            ldsm_x4(a0, a1, a2, a3, a_base + k0 * 2);
#pragma unroll
            for (int fp = 0; fp < 4; fp++) {
                uint32_t b0, b1, b2, b3;
                ldsm_x4(b0, b1, b2, b3, b_base + (fp * 16 * 72 + k0) * 2);
                mma_fp16(c[2 * fp],     a0, a1, a2, a3, b0, b2);
                mma_fp16(c[2 * fp + 1], a0, a1, a2, a3, b1, b3);
            }
        }
        __syncthreads();
    }
#pragma unroll
    for (int f = 0; f < 8; f++) {
        const int col = n0 + f * 8 + 2 * t;
        const int row0 = m0 + mw + g;
        if (mode == 0) {
            *reinterpret_cast<uint32_t*>(g_Q + (size_t)row0 * DIM + col) =
                packh2(c[f][0], c[f][1]);
            *reinterpret_cast<uint32_t*>(g_Q + (size_t)(row0 + 8) * DIM + col) =
                packh2(c[f][2], c[f][3]);
        } else {
            float b0 = bias[col], b1 = bias[col + 1];
            *reinterpret_cast<float2*>(Cf + (size_t)row0 * DIM + col) =
                make_float2(c[f][0] + b0, c[f][1] + b1);
            *reinterpret_cast<float2*>(Cf + (size_t)(row0 + 8) * DIM + col) =
                make_float2(c[f][2] + b0, c[f][3] + b1);
        }
    }
}

// ---------------------------------------------------------------------------
// K2: g_QK = g_Q_h @ Wk_h (K=64, one chunk). B direct layout + trans-ldsm.
// grid (8 e-chunks, 128 mtiles, 8 heads)
// ---------------------------------------------------------------------------
__global__ __launch_bounds__(256) void qk16_kernel()
{
    extern __shared__ __half smh[];
    __half* As = smh;               // [128][72]  A[r=(b,i)][k=d]
    __half* Bs = smh + 128 * 72;    // [64][72]   B[k=d][n=e]  (direct Wk layout)

    const int n0 = blockIdx.x * 64;
    const int m0 = blockIdx.y * 128;
    const int h  = blockIdx.z;
    const int tid = threadIdx.x;
    const int warp = tid >> 5, lane = tid & 31;
    const int g = lane >> 2, t = lane & 3;
    const int mw = warp * 16;
    const int l15 = lane & 15, lhi = (lane >> 4) * 8;

#pragma unroll
    for (int it = 0; it < 4; it++) {
        int idx = tid + it * 256; int r = idx >> 3, q = idx & 7;
        *reinterpret_cast<uint4*>(As + r * 72 + q * 8) =
            *reinterpret_cast<const uint4*>(g_Q + (size_t)(m0 + r) * DIM + h * DH + q * 8);
    }
#pragma unroll
    for (int it = 0; it < 2; it++) {
        int idx = tid + it * 256; int r = idx >> 3, q = idx & 7;
        *reinterpret_cast<uint4*>(Bs + r * 72 + q * 8) =
            *reinterpret_cast<const uint4*>(g_Wkh + (size_t)(h * DH + r) * DIM + n0 + q * 8);
    }
    __syncthreads();

    const uint32_t a_base = sm_u32(As) + (uint32_t)((mw + l15) * 72 + lhi) * 2;
    const uint32_t b_base = sm_u32(Bs) + (uint32_t)(l15 * 72 + lhi) * 2;

    float c[8][4];
#pragma unroll
    for (int f = 0; f < 8; f++)
#pragma unroll
        for (int e = 0; e < 4; e++) c[f][e] = 0.f;

#pragma unroll
    for (int ks = 0; ks < 4; ks++) {
        const int k0 = ks * 16;
        uint32_t a0, a1, a2, a3;
        ldsm_x4(a0, a1, a2, a3, a_base + k0 * 2);
#pragma unroll
        for (int fp = 0; fp < 4; fp++) {
            uint32_t b0, b1, b2, b3;
            // trans: stored rows = k (d), cols = n (e); b-pairs (b0,b1), (b2,b3)
            ldsm_x4t(b0, b1, b2, b3, b_base + (k0 * 72 + fp * 16) * 2);
            mma_fp16(c[2 * fp],     a0, a1, a2, a3, b0, b1);
            mma_fp16(c[2 * fp + 1], a0, a1, a2, a3, b2, b3);
        }
    }

    const int bb = (m0 + mw) >> 4;
#pragma unroll
    for (int f = 0; f < 8; f++) {
        const int col = n0 + f * 8 + 2 * t;
        size_t o0 = (((size_t)bb * NHEAD + h) * NTOK + g) * DIM + col;
        size_t o1 = (((size_t)bb * NHEAD + h) * NTOK + g + 8) * DIM + col;
        *reinterpret_cast<uint32_t*>(g_QK + o0) = packh2(c[f][0], c[f][1]);
        *reinterpret_cast<uint32_t*>(g_QK + o1) = packh2(c[f][2], c[f][3]);
    }
}

// ---------------------------------------------------------------------------
// K3: per-batch attention. warp = head. Phase B uses trans-ldsm.
// ---------------------------------------------------------------------------
__global__ __launch_bounds__(256) void attn_kernel(const float* __restrict__ l)
{
    extern __shared__ __half smh[];
    __half* l_s  = smh;                    // [128][72]  l[j][e-chunk]
    __half* qk_s = smh + 128 * 72;         // [128][72]
    __half* s_s  = qk_s + 128 * 72;        // [128][136]

    const int b = blockIdx.x;
    const int m = b & (NLAT - 1);
    const int njt = (m >> 5) + 1;
    const int rows = njt << 5;

    const int tid = threadIdx.x;
    const int h = tid >> 5, lane = tid & 31;
    const int g = lane >> 2, t = lane & 3;
    const int l15 = lane & 15, lhi = (lane >> 4) * 8;

    const float*  lb  = l + (size_t)b * NLAT * DIM;
    const __half* qkb = g_QK + (size_t)b * NHEAD * NTOK * DIM;

    const uint32_t aq_base  = sm_u32(qk_s) + (uint32_t)((h * 16 + l15) * 72 + lhi) * 2;
    const uint32_t blA_base = sm_u32(l_s)  + (uint32_t)(l15 * 72 + lhi) * 2;

    float cs[16][4];
#pragma unroll
    for (int f = 0; f < 16; f++)
#pragma unroll
        for (int e = 0; e < 4; e++) cs[f][e] = 0.f;

    // ---- phase A: scores = qk @ l^T ----
    for (int ec = 0; ec < 8; ec++) {
        const int e0 = ec * 64;
#pragma unroll
        for (int it = 0; it < 4; it++) {
            int idx = tid + it * 256; int r = idx >> 3, q = idx & 7;
            *reinterpret_cast<uint4*>(qk_s + r * 72 + q * 8) =
                *reinterpret_cast<const uint4*>(qkb + (size_t)r * DIM + e0 + q * 8);
        }
#pragma unroll
        for (int it = 0; it < 8; it++) {
            int idx = tid + it * 256; int r = idx >> 4, c4 = idx & 15;
            if (r < rows) {
                float4 v = *reinterpret_cast<const float4*>(
                    lb + (size_t)r * DIM + e0 + c4 * 4);
                *reinterpret_cast<uint2*>(l_s + r * 72 + c4 * 4) = pack4(v);
            }
        }
        __syncthreads();
#pragma unroll
        for (int ks = 0; ks < 4; ks++) {
            const int k0 = ks * 16;
            uint32_t a0, a1, a2, a3;
            ldsm_x4(a0, a1, a2, a3, aq_base + k0 * 2);
#pragma unroll
            for (int jt = 0; jt < 4; jt++) {
                if (jt < njt) {
#pragma unroll
                    for (int jp = 0; jp < 2; jp++) {
                        uint32_t b0, b1, b2, b3;
                        ldsm_x4(b0, b1, b2, b3,
                                blA_base + ((jt * 32 + jp * 16) * 72 + k0) * 2);
                        mma_fp16(cs[jt * 4 + jp * 2],     a0, a1, a2, a3, b0, b2);
                        mma_fp16(cs[jt * 4 + jp * 2 + 1], a0, a1, a2, a3, b1, b3);
                    }
                }
            }
        }
        __syncthreads();
    }

    // ---- masked softmax (rows g, g+8 per thread) ----
    float mx0 = -1e30f, mx1 = -1e30f;
#pragma unroll
    for (int f = 0; f < 16; f++) {
        const int jb = f * 8 + 2 * t;
#pragma unroll
        for (int e = 0; e < 2; e++) {
            if (jb + e > m) { cs[f][e] = -1e30f; cs[f][2 + e] = -1e30f; }
            mx0 = fmaxf(mx0, cs[f][e]);
            mx1 = fmaxf(mx1, cs[f][2 + e]);
        }
    }
    mx0 = fmaxf(mx0, __shfl_xor_sync(0xffffffffu, mx0, 1));
    mx0 = fmaxf(mx0, __shfl_xor_sync(0xffffffffu, mx0, 2));
    mx1 = fmaxf(mx1, __shfl_xor_sync(0xffffffffu, mx1, 1));
    mx1 = fmaxf(mx1, __shfl_xor_sync(0xffffffffu, mx1, 2));
    float s0 = 0.f, s1 = 0.f;
#pragma unroll
    for (int f = 0; f < 16; f++)
#pragma unroll
        for (int e = 0; e < 2; e++) {
            cs[f][e] = __expf(cs[f][e] - mx0);         s0 += cs[f][e];
            cs[f][2 + e] = __expf(cs[f][2 + e] - mx1); s1 += cs[f][2 + e];
        }
    s0 += __shfl_xor_sync(0xffffffffu, s0, 1);
    s0 += __shfl_xor_sync(0xffffffffu, s0, 2);
    s1 += __shfl_xor_sync(0xffffffffu, s1, 1);
    s1 += __shfl_xor_sync(0xffffffffu, s1, 2);
    const float i0 = 1.f / s0, i1 = 1.f / s1;
#pragma unroll
    for (int f = 0; f < 16; f++) {
        const int jb = f * 8 + 2 * t;
        *reinterpret_cast<uint32_t*>(s_s + (h * 16 + g) * 136 + jb) =
            packh2(cs[f][0] * i0, cs[f][1] * i0);
        *reinterpret_cast<uint32_t*>(s_s + (h * 16 + g + 8) * 136 + jb) =
            packh2(cs[f][2] * i1, cs[f][3] * i1);
    }
    __syncwarp();   // s_s rows are warp-private; make writes visible to ldsm

    // ---- phase B: AL = attn @ l (B via trans-ldsm on [j][e] layout) ----
    const uint32_t as_base  = sm_u32(s_s) + (uint32_t)((h * 16 + l15) * 136 + lhi) * 2;
    const uint32_t blB_base = sm_u32(l_s) + (uint32_t)(l15 * 72 + lhi) * 2;

    for (int ec = 0; ec < 8; ec++) {
        const int e0 = ec * 64;
        __syncthreads();                   // previous consumers of l_s done
#pragma unroll
        for (int it = 0; it < 8; it++) {
            int idx = tid + it * 256; int r = idx >> 4, c4 = idx & 15;
            if (r < rows) {
                float4 v = *reinterpret_cast<const float4*>(
                    lb + (size_t)r * DIM + e0 + c4 * 4);
                *reinterpret_cast<uint2*>(l_s + r * 72 + c4 * 4) = pack4(v);
            }
        }
        __syncthreads();

        float co[8][4];
#pragma unroll
        for (int en = 0; en < 8; en++)
#pragma unroll
            for (int e = 0; e < 4; e++) co[en][e] = 0.f;

        for (int jk = 0; jk < njt * 2; jk++) {
            const int k0 = jk * 16;        // j offset
            uint32_t a0, a1, a2, a3;
            ldsm_x4(a0, a1, a2, a3, as_base + k0 * 2);
#pragma unroll
            for (int ep = 0; ep < 4; ep++) {
                uint32_t b0, b1, b2, b3;
                // trans: stored rows = k (j), cols = n (e); pairs (b0,b1), (b2,b3)
                ldsm_x4t(b0, b1, b2, b3, blB_base + (k0 * 72 + ep * 16) * 2);
                mma_fp16(co[2 * ep],     a0, a1, a2, a3, b0, b1);
                mma_fp16(co[2 * ep + 1], a0, a1, a2, a3, b2, b3);
            }
        }
#pragma unroll
        for (int en = 0; en < 8; en++) {
            const int col = e0 + en * 8 + 2 * t;
            size_t o0 = ((size_t)b * (NHEAD * NTOK) + h * 16 + g) * DIM + col;
            size_t o1 = ((size_t)b * (NHEAD * NTOK) + h * 16 + g + 8) * DIM + col;
            *reinterpret_cast<uint32_t*>(g_AL + o0) = packh2(co[en][0], co[en][1]);
            *reinterpret_cast<uint32_t*>(g_AL + o1) = packh2(co[en][2], co[en][3]);
        }
    }
}

// ---------------------------------------------------------------------------
// K4: g_OV = g_AL_h @ Wv_h^T  (K=512). Double-buffered cp.async. grid (128, 8)
// ---------------------------------------------------------------------------
__global__ __launch_bounds__(256) void ov16_kernel()
{
    extern __shared__ __half smh[];
    const int bt = blockIdx.x;
    const int h  = blockIdx.y;
    const int tid = threadIdx.x;
    const int warp = tid >> 5, lane = tid & 31;
    const int g = lane >> 2, t = lane & 3;
    const int mw = warp * 16;
    const int l15 = lane & 15, lhi = (lane >> 4) * 8;

    auto stage = [&](int kc, int s) {
        __half* As = smh + s * GEMM_BUF_H;
        __half* Ws = As + 128 * 72;
        const int k0g = kc * 64;
#pragma unroll
        for (int it = 0; it < 4; it++) {
            int idx = tid + it * 256; int r = idx >> 3, q = idx & 7;
            size_t gr = (((size_t)(bt * 8 + (r >> 4)) * NHEAD + h) * NTOK + (r & 15));
            cp16(sm_u32(As + r * 72 + q * 8), g_AL + gr * DIM + k0g + q * 8);
        }
#pragma unroll
        for (int it = 0; it < 2; it++) {
            int idx = tid + it * 256; int r = idx >> 3, q = idx & 7;
            cp16(sm_u32(Ws + r * 72 + q * 8),
                 g_Wvh + (size_t)(h * DH + r) * DIM + k0g + q * 8);
        }
        cp_commit();
    };

    float c[8][4];
#pragma unroll
    for (int f = 0; f < 8; f++)
#pragma unroll
        for (int e = 0; e < 4; e++) c[f][e] = 0.f;

    stage(0, 0);
    for (int kc = 0; kc < 8; kc++) {
        if (kc < 7) {
            stage(kc + 1, (kc + 1) & 1);
            asm volatile("cp.async.wait_group 1;");
        } else {
            asm volatile("cp.async.wait_group 0;");
        }
        __syncthreads();
        __half* As = smh + (kc & 1) * GEMM_BUF_H;
        __half* Ws = As + 128 * 72;
        const uint32_t a_base = sm_u32(As) + (uint32_t)((mw + l15) * 72 + lhi) * 2;
        const uint32_t b_base = sm_u32(Ws) + (uint32_t)(l15 * 72 + lhi) * 2;
#pragma unroll
        for (int ks = 0; ks < 4; ks++) {
            const int k0 = ks * 16;
            uint32_t a0, a1, a2, a3;
            ldsm_x4(a0, a1, a2, a3, a_base + k0 * 2);
#pragma unroll
            for (int fp = 0; fp < 4; fp++) {
                uint32_t b0, b1, b2, b3;
                ldsm_x4(b0, b1, b2, b3, b_base + (fp * 16 * 72 + k0) * 2);
                mma_fp16(c[2 * fp],     a0, a1, a2, a3, b0, b2);
                mma_fp16(c[2 * fp + 1], a0, a1, a2, a3, b1, b3);
            }
        }
        __syncthreads();
    }

    const int bb = bt * 8 + warp;
#pragma unroll
    for (int f = 0; f < 8; f++) {
        const int col = h * DH + f * 8 + 2 * t;
        size_t o0 = ((size_t)bb * NTOK + g) * DIM + col;
        size_t o1 = ((size_t)bb * NTOK + g + 8) * DIM + col;
        *reinterpret_cast<uint32_t*>(g_OV + o0) = packh2(c[f][0], c[f][1]);
        *reinterpret_cast<uint32_t*>(g_OV + o1) = packh2(c[f][2], c[f][3]);
    }
}

// ---------------------------------------------------------------------------
extern "C" void kernel_launch(void* const* d_in, const int* in_sizes, int n_in,
                              void* d_out, int out_size)
{
    const float* x  = (const float*)d_in[0];
    const float* l  = (const float*)d_in[1];
    const float* Wq = (const float*)d_in[2];
    const float* Wk = (const float*)d_in[3];
    const float* Wv = (const float*)d_in[4];
    const float* Wo = (const float*)d_in[5];
    const float* bo = (const float*)d_in[6];
    float* out = (float*)d_out;

    const int smem_attn = ATTN_SMEM_H * 2;
    cudaFuncSetAttribute(proj16_kernel, cudaFuncAttributeMaxDynamicSharedMemorySize, GEMM_SMEM);
    cudaFuncSetAttribute(qk16_kernel,   cudaFuncAttributeMaxDynamicSharedMemorySize, QK_SMEM);
    cudaFuncSetAttribute(attn_kernel,   cudaFuncAttributeMaxDynamicSharedMemorySize, smem_attn);
    cudaFuncSetAttribute(ov16_kernel,   cudaFuncAttributeMaxDynamicSharedMemorySize, GEMM_SMEM);

    // K0: conversions (x: 2M float4, then 4 x 64K float4)
    const int NX4 = (NB * NTOK * DIM) / 4;
    const int prep_blocks = (NX4 + 4 * 65536) / 256;
    prep_kernel<<<prep_blocks, 256>>>(x, Wq, Wk, Wv, Wo);
    // K1: Q = g_X @ (0.125 Wq)^T
    proj16_kernel<<<dim3(8, 128), 256, GEMM_SMEM>>>(0, nullptr, nullptr);
    // K2: QK = q_h @ Wk_h
    qk16_kernel<<<dim3(8, 128, 8), 256, QK_SMEM>>>();
    // K3: attention per batch
    attn_kernel<<<1024, 256, smem_attn>>>(l);
    // K4: OV = AL_h @ Wv_h^T
    ov16_kernel<<<dim3(128, 8), 256, GEMM_SMEM>>>();
    // K5: out = OV @ Wo^T + bo
    proj16_kernel<<<dim3(8, 128), 256, GEMM_SMEM>>>(1, out, bo);
}